// round 8
// baseline (speedup 1.0000x reference)
#include <cuda_runtime.h>

// Problem constants
#define BB   1024
#define NN   64
#define CDIM 256
#define HH   8
#define OO   64
#define THREADS 512

// smem padding
#define XPAD  260   // x row stride (floats)
#define QPAD  68    // q/k/v/scores/adj row stride
#define WTPAD 198   // staged-W row stride (6 mod 32 banks -> 2-way STS, float2-aligned ONLY)

// smem layout (floats)
#define OFF_XS   0
#define OFF_WT0  (OFF_XS + 64*XPAD)           // 16640
#define OFF_WT1  (OFF_WT0 + 32*WTPAD)
#define OFF_QS   (OFF_WT1 + 32*WTPAD)
#define OFF_KS   (OFF_QS + 64*QPAD)
#define OFF_VS   (OFF_KS + 64*QPAD)
#define OFF_SS   (OFF_VS + 64*QPAD)
#define OFF_AD   (OFF_SS + 64*QPAD)
#define OFF_EC   (OFF_AD + 64*QPAD)
#define OFF_QE   (OFF_EC + 64)
#define OFF_EW   (OFF_QE + 64)
#define SMEM_FLOATS (OFF_EW + 64)             // 51264 floats = 205056 bytes

__global__ __launch_bounds__(THREADS, 1)
void graphlearner_kernel(const float* __restrict__ ctx, const float* __restrict__ adj,
                         const float* __restrict__ Wq, const float* __restrict__ bq,
                         const float* __restrict__ Wk, const float* __restrict__ bk,
                         const float* __restrict__ Wv, const float* __restrict__ bv,
                         const float* __restrict__ We, const float* __restrict__ Ws,
                         const float* __restrict__ bs, float* __restrict__ out)
{
    extern __shared__ float sm[];
    float* xs   = sm + OFF_XS;   // [64][XPAD]
    float* wt0  = sm + OFF_WT0;  // staged weights buffer 0 [kk][col]
    float* wt1  = sm + OFF_WT1;  // staged weights buffer 1
    float* qs   = sm + OFF_QS;
    float* ks   = sm + OFF_KS;
    float* vs   = sm + OFF_VS;
    float* ss   = sm + OFF_SS;   // scores -> alpha
    float* ad   = sm + OFF_AD;   // adjT: ad[i][j] = adj[b][j][i]
    float* ec   = sm + OFF_EC;
    float* qe   = sm + OFF_QE;
    float* ews  = sm + OFF_EW;

    const int b = blockIdx.x;
    const int t = threadIdx.x;

    // GEMM mapping: warp owns 4 rows (broadcast a); lane owns col-pair 2*txg,
    // 2*txg+1 inside EACH of q/k/v -> conflict-free float2 b-loads.
    const int txg = t & 31;
    const int tyg = t >> 5;        // warp id 0..15
    const int i0g = tyg * 4;
    const int cp  = 2 * txg;       // col-pair base within each 64-wide matrix

    // 2x4 mapping for scores/AV/skip/epilogue
    const int tx8 = t & 15;
    const int ty8 = t >> 4;        // 0..31
    const int i02 = ty8 * 2;
    const int o0  = tx8 * 4;

    // 8-threads-per-row mapping (qe / softmax)
    const int rw  = t >> 3;        // row 0..63
    const int oct = t & 7;

    // ---- load x_b (float4, coalesced) ----
    {
        const float4* xg = (const float4*)(ctx + (size_t)b * (NN * CDIM));
        for (int l = t; l < NN * CDIM / 4; l += THREADS) {
            int e = l * 4;
            int i = e >> 8;
            int k = e & 255;
            float4 v4 = xg[l];
            float* d = &xs[i * XPAD + k];
            d[0] = v4.x; d[1] = v4.y; d[2] = v4.z; d[3] = v4.w;
        }
    }
    // ---- load adjT ----
    {
        const float* ag = adj + (size_t)b * (NN * NN);
        for (int l = t; l < NN * NN; l += THREADS) {
            int j = l >> 6, i = l & 63;
            ad[i * QPAD + j] = ag[l];
        }
    }

    // persistent attention-out accumulator (2 rows x 4 cols)
    float outr[2][4];
#pragma unroll
    for (int r = 0; r < 2; r++)
#pragma unroll
        for (int c = 0; c < 4; c++) outr[r][c] = 0.f;

    for (int h = 0; h < HH; ++h) {
        if (t < 64) ews[t] = We[h * 64 + t];

        // ================= QKV projection GEMM (64x192x256) =================
        // acc[r][2m+p]: matrix m (0=q,1=k,2=v), col cp+p
        float acc[4][6];
#pragma unroll
        for (int r = 0; r < 4; r++)
#pragma unroll
            for (int c = 0; c < 6; c++) acc[r][c] = 0.f;

        const int hbase = h * 64;
        {
            // prologue stage into wt0 (k0 = 0); kk-fast => coalesced LDG
            for (int l = t; l < 192 * 32; l += THREADS) {
                int kk = l & 31, col = l >> 5;
                int m = col >> 6, o = col & 63;
                const float* Wm = (m == 0) ? Wq : (m == 1) ? Wk : Wv;
                wt0[kk * WTPAD + col] = Wm[(hbase + o) * CDIM + kk];
            }
        }
        __syncthreads();

        for (int kb = 0; kb < 8; kb++) {
            const int k0 = kb * 32;
            float* cur = (kb & 1) ? wt1 : wt0;
            float* nxt = (kb & 1) ? wt0 : wt1;
            if (kb < 7) {
                const int kn = k0 + 32;
                for (int l = t; l < 192 * 32; l += THREADS) {
                    int kk = l & 31, col = l >> 5;
                    int m = col >> 6, o = col & 63;
                    const float* Wm = (m == 0) ? Wq : (m == 1) ? Wk : Wv;
                    nxt[kk * WTPAD + col] = Wm[(hbase + o) * CDIM + kn + kk];
                }
            }
#pragma unroll
            for (int kk = 0; kk < 32; kk += 4) {
                float4 a4[4];
#pragma unroll
                for (int r = 0; r < 4; r++)
                    a4[r] = *(const float4*)&xs[(i0g + r) * XPAD + k0 + kk];
#pragma unroll
                for (int u = 0; u < 4; u++) {
                    const float* wrow = &cur[(kk + u) * WTPAD];
                    float2 b0 = *(const float2*)&wrow[cp];          // q cols
                    float2 b1 = *(const float2*)&wrow[64 + cp];     // k cols
                    float2 b2 = *(const float2*)&wrow[128 + cp];    // v cols
#pragma unroll
                    for (int r = 0; r < 4; r++) {
                        float av = ((const float*)&a4[r])[u];
                        acc[r][0] += av * b0.x;
                        acc[r][1] += av * b0.y;
                        acc[r][2] += av * b1.x;
                        acc[r][3] += av * b1.y;
                        acc[r][4] += av * b2.x;
                        acc[r][5] += av * b2.y;
                    }
                }
            }
            __syncthreads();
        }

        // write q/k/v (+bias) to smem: conflict-free float2 stores
#pragma unroll
        for (int m = 0; m < 3; m++) {
            const float* bm = (m == 0) ? bq : (m == 1) ? bk : bv;
            float* dst = (m == 0) ? qs : (m == 1) ? ks : vs;
            float b0 = bm[hbase + cp];
            float b1 = bm[hbase + cp + 1];
#pragma unroll
            for (int r = 0; r < 4; r++) {
                float2 v2 = make_float2(acc[r][2 * m] + b0, acc[r][2 * m + 1] + b1);
                *(float2*)&dst[(i0g + r) * QPAD + cp] = v2;
            }
        }
        __syncthreads();

        // ================= qe[i] = q_i . ew (8 threads/row) =================
        {
            const float* qrow = &qs[rw * QPAD + oct * 8];
            const float* erow = &ews[oct * 8];
            float p = 0.f;
#pragma unroll
            for (int u = 0; u < 8; u++) p += qrow[u] * erow[u];
            p += __shfl_xor_sync(0xffffffffu, p, 1);
            p += __shfl_xor_sync(0xffffffffu, p, 2);
            p += __shfl_xor_sync(0xffffffffu, p, 4);
            if (oct == 0) qe[rw] = p;
        }
        __syncthreads();

        // ================= scores S = (q k^T + adjT*qe)/8 (2x4 tile) =================
        {
            float sa[2][4];
#pragma unroll
            for (int r = 0; r < 2; r++)
#pragma unroll
                for (int c = 0; c < 4; c++) sa[r][c] = 0.f;
#pragma unroll
            for (int o = 0; o < 64; o += 4) {
                float4 aq[2], bk4[4];
#pragma unroll
                for (int r = 0; r < 2; r++) aq[r]  = *(const float4*)&qs[(i02 + r) * QPAD + o];
#pragma unroll
                for (int c = 0; c < 4; c++) bk4[c] = *(const float4*)&ks[(o0 + c) * QPAD + o];
#pragma unroll
                for (int r = 0; r < 2; r++)
#pragma unroll
                    for (int c = 0; c < 4; c++)
                        sa[r][c] += aq[r].x * bk4[c].x + aq[r].y * bk4[c].y
                                  + aq[r].z * bk4[c].z + aq[r].w * bk4[c].w;
            }
#pragma unroll
            for (int r = 0; r < 2; r++) {
                float qei = qe[i02 + r];
#pragma unroll
                for (int c = 0; c < 4; c++)
                    ss[(i02 + r) * QPAD + o0 + c] =
                        0.125f * (sa[r][c] + ad[(i02 + r) * QPAD + o0 + c] * qei);
            }
        }
        __syncthreads();

        // ================= softmax over j (8 threads/row) + ecoef =================
        {
            float* row = &ss[rw * QPAD + oct * 8];
            const float* arow = &ad[rw * QPAD + oct * 8];
            float m = -1e30f;
#pragma unroll
            for (int u = 0; u < 8; u++) m = fmaxf(m, row[u]);
            m = fmaxf(m, __shfl_xor_sync(0xffffffffu, m, 1));
            m = fmaxf(m, __shfl_xor_sync(0xffffffffu, m, 2));
            m = fmaxf(m, __shfl_xor_sync(0xffffffffu, m, 4));
            float e[8];
            float s = 0.f;
#pragma unroll
            for (int u = 0; u < 8; u++) { e[u] = __expf(row[u] - m); s += e[u]; }
            s += __shfl_xor_sync(0xffffffffu, s, 1);
            s += __shfl_xor_sync(0xffffffffu, s, 2);
            s += __shfl_xor_sync(0xffffffffu, s, 4);
            float rinv = 1.f / s;
            float pc = 0.f;
#pragma unroll
            for (int u = 0; u < 8; u++) {
                float al = e[u] * rinv;
                row[u] = al;
                pc += al * arow[u];
            }
            pc += __shfl_xor_sync(0xffffffffu, pc, 1);
            pc += __shfl_xor_sync(0xffffffffu, pc, 2);
            pc += __shfl_xor_sync(0xffffffffu, pc, 4);
            if (oct == 0) ec[rw] = pc;
        }
        __syncthreads();

        // ================= out += alpha @ v  +  ec_i * ew_o =================
        {
            float sa[2][4];
#pragma unroll
            for (int r = 0; r < 2; r++)
#pragma unroll
                for (int c = 0; c < 4; c++) sa[r][c] = 0.f;
#pragma unroll 8
            for (int j = 0; j < 64; j++) {
                float4 bv4 = *(const float4*)&vs[j * QPAD + o0];
#pragma unroll
                for (int r = 0; r < 2; r++) {
                    float al = ss[(i02 + r) * QPAD + j];
                    sa[r][0] += al * bv4.x;
                    sa[r][1] += al * bv4.y;
                    sa[r][2] += al * bv4.z;
                    sa[r][3] += al * bv4.w;
                }
            }
#pragma unroll
            for (int r = 0; r < 2; r++) {
                float eci = ec[i02 + r];
#pragma unroll
                for (int c = 0; c < 4; c++)
                    outr[r][c] += sa[r][c] + eci * ews[o0 + c];
            }
        }
        __syncthreads();  // before next head overwrites qs/ks/vs/ss/ews
    }

    // ================= skip GEMM: sk = x @ Ws^T (2x4 tile, ping-pong) =================
    float sk[2][4];
#pragma unroll
    for (int r = 0; r < 2; r++)
#pragma unroll
        for (int c = 0; c < 4; c++) sk[r][c] = 0.f;

    for (int l = t; l < 64 * 32; l += THREADS) {
        int kk = l & 31, o = l >> 5;
        wt0[kk * WTPAD + o] = Ws[o * CDIM + kk];
    }
    __syncthreads();

    for (int kb = 0; kb < 8; kb++) {
        const int k0 = kb * 32;
        float* cur = (kb & 1) ? wt1 : wt0;
        float* nxt = (kb & 1) ? wt0 : wt1;
        if (kb < 7) {
            const int kn = k0 + 32;
            for (int l = t; l < 64 * 32; l += THREADS) {
                int kk = l & 31, o = l >> 5;
                nxt[kk * WTPAD + o] = Ws[o * CDIM + kn + kk];
            }
        }
#pragma unroll
        for (int kk = 0; kk < 32; kk += 4) {
            float4 a4[2];
#pragma unroll
            for (int r = 0; r < 2; r++)
                a4[r] = *(const float4*)&xs[(i02 + r) * XPAD + k0 + kk];
#pragma unroll
            for (int u = 0; u < 4; u++) {
                // WTPAD is 2 mod 4 -> float4 here would be misaligned on odd rows.
                // Use two float2 loads (always 8B-aligned: even stride, even o0).
                const float* brow = &cur[(kk + u) * WTPAD + o0];
                float2 bl = *(const float2*)(brow);
                float2 bh = *(const float2*)(brow + 2);
#pragma unroll
                for (int r = 0; r < 2; r++) {
                    float av = ((const float*)&a4[r])[u];
                    sk[r][0] += av * bl.x;
                    sk[r][1] += av * bl.y;
                    sk[r][2] += av * bh.x;
                    sk[r][3] += av * bh.y;
                }
            }
        }
        __syncthreads();
    }

    // ================= epilogue =================
    {
        float4* og = (float4*)(out + (size_t)b * (NN * OO));
#pragma unroll
        for (int r = 0; r < 2; r++) {
            float4 res;
            float v0 = outr[r][0] * 0.125f + sk[r][0] + bs[o0 + 0];
            float v1 = outr[r][1] * 0.125f + sk[r][1] + bs[o0 + 1];
            float v2 = outr[r][2] * 0.125f + sk[r][2] + bs[o0 + 2];
            float v3 = outr[r][3] * 0.125f + sk[r][3] + bs[o0 + 3];
            res.x = (v0 > 0.1f) ? 1.f / (1.f + __expf(-v0)) : 0.f;
            res.y = (v1 > 0.1f) ? 1.f / (1.f + __expf(-v1)) : 0.f;
            res.z = (v2 > 0.1f) ? 1.f / (1.f + __expf(-v2)) : 0.f;
            res.w = (v3 > 0.1f) ? 1.f / (1.f + __expf(-v3)) : 0.f;
            og[(i02 + r) * 16 + tx8] = res;
        }
    }
}

extern "C" void kernel_launch(void* const* d_in, const int* in_sizes, int n_in,
                              void* d_out, int out_size)
{
    const float* ctx = (const float*)d_in[0];
    const float* adj = (const float*)d_in[1];
    const float* Wq  = (const float*)d_in[2];
    const float* bq  = (const float*)d_in[3];
    const float* Wk  = (const float*)d_in[4];
    const float* bk  = (const float*)d_in[5];
    const float* Wv  = (const float*)d_in[6];
    const float* bv  = (const float*)d_in[7];
    const float* We  = (const float*)d_in[8];
    const float* Ws  = (const float*)d_in[9];
    const float* bs  = (const float*)d_in[10];
    float* out = (float*)d_out;

    const int smem_bytes = SMEM_FLOATS * sizeof(float);
    cudaFuncSetAttribute(graphlearner_kernel,
                         cudaFuncAttributeMaxDynamicSharedMemorySize, smem_bytes);
    graphlearner_kernel<<<BB, THREADS, smem_bytes>>>(ctx, adj, Wq, bq, Wk, bk, Wv, bv,
                                                     We, Ws, bs, out);
}

// round 15
// speedup vs baseline: 1.2149x; 1.2149x over previous
#include <cuda_runtime.h>
#include <cstdint>

// ============================================================================
// Problem constants
// ============================================================================
#define BB    1024
#define NN    64
#define CDIM  256
#define HH    8
#define OO    64

// ============================================================================
// Scratch (device global -- allocation-free per harness rules)
// ============================================================================
#define NXROWS (BB * NN)           // 65536
__device__ float g_qkv[(size_t)NXROWS * 1536];   // [65536][1536] fp32

// ============================================================================
// tf32 helpers (base-target PTX, sm_80+; no 'a' features)
// ============================================================================
__device__ __forceinline__ uint32_t f2tf32(float v) {
    uint32_t r;
    asm("cvt.rna.tf32.f32 %0, %1;" : "=r"(r) : "f"(v));
    return r;
}

__device__ __forceinline__ void mma_tf32(float c[4], const uint32_t a[4],
                                         uint32_t b0, uint32_t b1) {
    asm volatile(
        "mma.sync.aligned.m16n8k8.row.col.f32.tf32.tf32.f32 "
        "{%0,%1,%2,%3}, {%4,%5,%6,%7}, {%8,%9}, {%0,%1,%2,%3};"
        : "+f"(c[0]), "+f"(c[1]), "+f"(c[2]), "+f"(c[3])
        : "r"(a[0]), "r"(a[1]), "r"(a[2]), "r"(a[3]), "r"(b0), "r"(b1));
}

// ============================================================================
// K1: QKV projection GEMM, 3xTF32 via mma.sync (HMMA fallback path)
//   D[65536,1536] = X[65536,256] @ W^T  (W rows stacked: Wq 0-511, Wk, Wv)
//   CTA tile M=128, N=128, K chunked by 64. Split fp32->tf32 hi/lo on the fly.
//   Products: hh + hl + lh (3xTF32, ~fp32 accuracy).
// ============================================================================
#define K1_THREADS 256
#define APAD 68                       // u32 row stride (4 mod 32 banks)
// smem (u32): Ah[128*68] Ar Bh Br  => 4*8704 = 34816 u32 = 139264 B
#define K1_AH 0
#define K1_AR 8704
#define K1_BH 17408
#define K1_BR 26112
#define K1_SMEM_BYTES (34816 * 4)

__global__ __launch_bounds__(K1_THREADS, 1)
void qkv_gemm_kernel(const float* __restrict__ ctx,
                     const float* __restrict__ Wq,
                     const float* __restrict__ Wk,
                     const float* __restrict__ Wv)
{
    extern __shared__ uint32_t smu[];
    uint32_t* Ah = smu + K1_AH;
    uint32_t* Ar = smu + K1_AR;
    uint32_t* Bh = smu + K1_BH;
    uint32_t* Br = smu + K1_BR;

    const int t    = threadIdx.x;
    const int lane = t & 31;
    const int wid  = t >> 5;
    const int m0   = blockIdx.x * 128;
    const int by   = blockIdx.y;
    const int n0g  = by * 128;

    const float* Wsrc;
    int nrow0;
    if (by < 4)      { Wsrc = Wq; nrow0 = n0g; }
    else if (by < 8) { Wsrc = Wk; nrow0 = n0g - 512; }
    else             { Wsrc = Wv; nrow0 = n0g - 1024; }

    // warp grid 2x4: warp tile 64x32
    const int m_off = (wid >> 2) * 64;
    const int n_off = (wid & 3) * 32;
    const int gq = lane >> 2;   // groupID
    const int tg = lane & 3;    // thread-in-group

    float acc[4][4][4];
#pragma unroll
    for (int m = 0; m < 4; m++)
#pragma unroll
        for (int n = 0; n < 4; n++)
#pragma unroll
            for (int u = 0; u < 4; u++) acc[m][n][u] = 0.f;

    for (int kc = 0; kc < 4; ++kc) {
        const int k0 = kc * 64;
        __syncthreads();   // previous chunk's smem fully consumed
        // ---- stage A and B chunk: fp32 -> tf32 hi/lo ----
        for (int l = t; l < 2048; l += K1_THREADS) {
            int row = l >> 4, c4 = (l & 15) * 4;
            float4 av = *(const float4*)(ctx + (size_t)(m0 + row) * CDIM + k0 + c4);
            float4 bv = *(const float4*)(Wsrc + (size_t)(nrow0 + row) * CDIM + k0 + c4);
#pragma unroll
            for (int u = 0; u < 4; u++) {
                float va = ((const float*)&av)[u];
                uint32_t ha = f2tf32(va);
                Ah[row * APAD + c4 + u] = ha;
                Ar[row * APAD + c4 + u] = f2tf32(va - __uint_as_float(ha));
                float vb = ((const float*)&bv)[u];
                uint32_t hb = f2tf32(vb);
                Bh[row * APAD + c4 + u] = hb;
                Br[row * APAD + c4 + u] = f2tf32(vb - __uint_as_float(hb));
            }
        }
        __syncthreads();

        // ---- warp MMA over this chunk: 8 k-steps of 8 ----
#pragma unroll 1
        for (int k8 = 0; k8 < 8; ++k8) {
            const int kb = k8 * 8;
            uint32_t ah[4][4], ar[4][4];
#pragma unroll
            for (int m = 0; m < 4; m++) {
                int r0 = (m_off + m * 16 + gq) * APAD;
                int c0 = kb + tg;
                ah[m][0] = Ah[r0 + c0];
                ah[m][1] = Ah[r0 + 8 * APAD + c0];
                ah[m][2] = Ah[r0 + c0 + 4];
                ah[m][3] = Ah[r0 + 8 * APAD + c0 + 4];
                ar[m][0] = Ar[r0 + c0];
                ar[m][1] = Ar[r0 + 8 * APAD + c0];
                ar[m][2] = Ar[r0 + c0 + 4];
                ar[m][3] = Ar[r0 + 8 * APAD + c0 + 4];
            }
#pragma unroll
            for (int n = 0; n < 4; n++) {
                int nr = (n_off + n * 8 + gq) * APAD;
                int bc = kb + tg;
                uint32_t bh0 = Bh[nr + bc], bh1 = Bh[nr + bc + 4];
                uint32_t br0 = Br[nr + bc], br1 = Br[nr + bc + 4];
#pragma unroll
                for (int m = 0; m < 4; m++) {
                    mma_tf32(acc[m][n], ah[m], bh0, bh1);   // hi*hi
                    mma_tf32(acc[m][n], ah[m], br0, br1);   // hi*lo
                    mma_tf32(acc[m][n], ar[m], bh0, bh1);   // lo*hi
                }
            }
        }
    }

    // ---- writeback: accums -> smem (transpose) -> coalesced gmem ----
    __syncthreads();
    float* Ds = (float*)smu;   // [128][132] floats = 67584 B, fits in 139264
#pragma unroll
    for (int m = 0; m < 4; m++) {
        int r0 = m_off + m * 16 + gq;
#pragma unroll
        for (int n = 0; n < 4; n++) {
            int cb = n_off + n * 8 + 2 * tg;
            Ds[r0 * 132 + cb]           = acc[m][n][0];
            Ds[r0 * 132 + cb + 1]       = acc[m][n][1];
            Ds[(r0 + 8) * 132 + cb]     = acc[m][n][2];
            Ds[(r0 + 8) * 132 + cb + 1] = acc[m][n][3];
        }
    }
    __syncthreads();
    for (int l = t; l < 16384; l += K1_THREADS) {
        int r = l >> 7, c = l & 127;
        g_qkv[(size_t)(m0 + r) * 1536 + n0g + c] = Ds[r * 132 + c];
    }
}

// ============================================================================
// K2: attention + skip + epilogue (projection results loaded from g_qkv)
// ============================================================================
#define THREADS 512
#define XPAD  260
#define QPAD  68
#define WTPAD 198

#define OFF_XS   0
#define OFF_WT0  (OFF_XS + 64*XPAD)
#define OFF_WT1  (OFF_WT0 + 32*WTPAD)
#define OFF_QS   (OFF_WT1 + 32*WTPAD)
#define OFF_KS   (OFF_QS + 64*QPAD)
#define OFF_VS   (OFF_KS + 64*QPAD)
#define OFF_SS   (OFF_VS + 64*QPAD)
#define OFF_AD   (OFF_SS + 64*QPAD)
#define OFF_EC   (OFF_AD + 64*QPAD)
#define OFF_QE   (OFF_EC + 64)
#define OFF_EW   (OFF_QE + 64)
#define SMEM_FLOATS (OFF_EW + 64)

__global__ __launch_bounds__(THREADS, 1)
void attn_kernel(const float* __restrict__ ctx, const float* __restrict__ adj,
                 const float* __restrict__ bq, const float* __restrict__ bk,
                 const float* __restrict__ bv, const float* __restrict__ We,
                 const float* __restrict__ Ws, const float* __restrict__ bs,
                 float* __restrict__ out)
{
    extern __shared__ float sm[];
    float* xs   = sm + OFF_XS;
    float* wt0  = sm + OFF_WT0;
    float* wt1  = sm + OFF_WT1;
    float* qs   = sm + OFF_QS;
    float* ks   = sm + OFF_KS;
    float* vs   = sm + OFF_VS;
    float* ss   = sm + OFF_SS;
    float* ad   = sm + OFF_AD;
    float* ec   = sm + OFF_EC;
    float* qe   = sm + OFF_QE;
    float* ews  = sm + OFF_EW;

    const int b = blockIdx.x;
    const int t = threadIdx.x;

    const int tx8 = t & 15;
    const int ty8 = t >> 4;
    const int i02 = ty8 * 2;
    const int o0  = tx8 * 4;

    const int rw  = t >> 3;
    const int oct = t & 7;

    // ---- load x_b (for skip GEMM) ----
    {
        const float4* xg = (const float4*)(ctx + (size_t)b * (NN * CDIM));
        for (int l = t; l < NN * CDIM / 4; l += THREADS) {
            int e = l * 4;
            int i = e >> 8;
            int k = e & 255;
            float4 v4 = xg[l];
            float* d = &xs[i * XPAD + k];
            d[0] = v4.x; d[1] = v4.y; d[2] = v4.z; d[3] = v4.w;
        }
    }
    // ---- load adjT ----
    {
        const float* ag = adj + (size_t)b * (NN * NN);
        for (int l = t; l < NN * NN; l += THREADS) {
            int j = l >> 6, i = l & 63;
            ad[i * QPAD + j] = ag[l];
        }
    }

    float outr[2][4];
#pragma unroll
    for (int r = 0; r < 2; r++)
#pragma unroll
        for (int c = 0; c < 4; c++) outr[r][c] = 0.f;

    const float* qkv_b = g_qkv + (size_t)(b * NN) * 1536;

    for (int h = 0; h < HH; ++h) {
        const int hbase = h * 64;
        if (t < 64) ews[t] = We[hbase + t];

        // ---- load q/k/v (+bias) from scratch ----
        for (int l = t; l < 4096; l += THREADS) {
            int i = l >> 6, o = l & 63;
            const float* row = qkv_b + (size_t)i * 1536 + hbase + o;
            qs[i * QPAD + o] = row[0]    + bq[hbase + o];
            ks[i * QPAD + o] = row[512]  + bk[hbase + o];
            vs[i * QPAD + o] = row[1024] + bv[hbase + o];
        }
        __syncthreads();

        // ---- qe[i] = q_i . ew ----
        {
            const float* qrow = &qs[rw * QPAD + oct * 8];
            const float* erow = &ews[oct * 8];
            float p = 0.f;
#pragma unroll
            for (int u = 0; u < 8; u++) p += qrow[u] * erow[u];
            p += __shfl_xor_sync(0xffffffffu, p, 1);
            p += __shfl_xor_sync(0xffffffffu, p, 2);
            p += __shfl_xor_sync(0xffffffffu, p, 4);
            if (oct == 0) qe[rw] = p;
        }
        __syncthreads();

        // ---- scores S = (q k^T + adjT*qe)/8 ----
        {
            float sa[2][4];
#pragma unroll
            for (int r = 0; r < 2; r++)
#pragma unroll
                for (int c = 0; c < 4; c++) sa[r][c] = 0.f;
#pragma unroll
            for (int o = 0; o < 64; o += 4) {
                float4 aq[2], bk4[4];
#pragma unroll
                for (int r = 0; r < 2; r++) aq[r]  = *(const float4*)&qs[(i02 + r) * QPAD + o];
#pragma unroll
                for (int c = 0; c < 4; c++) bk4[c] = *(const float4*)&ks[(o0 + c) * QPAD + o];
#pragma unroll
                for (int r = 0; r < 2; r++)
#pragma unroll
                    for (int c = 0; c < 4; c++)
                        sa[r][c] += aq[r].x * bk4[c].x + aq[r].y * bk4[c].y
                                  + aq[r].z * bk4[c].z + aq[r].w * bk4[c].w;
            }
#pragma unroll
            for (int r = 0; r < 2; r++) {
                float qei = qe[i02 + r];
#pragma unroll
                for (int c = 0; c < 4; c++)
                    ss[(i02 + r) * QPAD + o0 + c] =
                        0.125f * (sa[r][c] + ad[(i02 + r) * QPAD + o0 + c] * qei);
            }
        }
        __syncthreads();

        // ---- softmax + ecoef ----
        {
            float* row = &ss[rw * QPAD + oct * 8];
            const float* arow = &ad[rw * QPAD + oct * 8];
            float m = -1e30f;
#pragma unroll
            for (int u = 0; u < 8; u++) m = fmaxf(m, row[u]);
            m = fmaxf(m, __shfl_xor_sync(0xffffffffu, m, 1));
            m = fmaxf(m, __shfl_xor_sync(0xffffffffu, m, 2));
            m = fmaxf(m, __shfl_xor_sync(0xffffffffu, m, 4));
            float e[8];
            float s = 0.f;
#pragma unroll
            for (int u = 0; u < 8; u++) { e[u] = __expf(row[u] - m); s += e[u]; }
            s += __shfl_xor_sync(0xffffffffu, s, 1);
            s += __shfl_xor_sync(0xffffffffu, s, 2);
            s += __shfl_xor_sync(0xffffffffu, s, 4);
            float rinv = 1.f / s;
            float pc = 0.f;
#pragma unroll
            for (int u = 0; u < 8; u++) {
                float al = e[u] * rinv;
                row[u] = al;
                pc += al * arow[u];
            }
            pc += __shfl_xor_sync(0xffffffffu, pc, 1);
            pc += __shfl_xor_sync(0xffffffffu, pc, 2);
            pc += __shfl_xor_sync(0xffffffffu, pc, 4);
            if (oct == 0) ec[rw] = pc;
        }
        __syncthreads();

        // ---- out += alpha @ v + ec_i * ew_o ----
        {
            float sa[2][4];
#pragma unroll
            for (int r = 0; r < 2; r++)
#pragma unroll
                for (int c = 0; c < 4; c++) sa[r][c] = 0.f;
#pragma unroll 8
            for (int j = 0; j < 64; j++) {
                float4 bv4 = *(const float4*)&vs[j * QPAD + o0];
#pragma unroll
                for (int r = 0; r < 2; r++) {
                    float al = ss[(i02 + r) * QPAD + j];
                    sa[r][0] += al * bv4.x;
                    sa[r][1] += al * bv4.y;
                    sa[r][2] += al * bv4.z;
                    sa[r][3] += al * bv4.w;
                }
            }
#pragma unroll
            for (int r = 0; r < 2; r++) {
                float eci = ec[i02 + r];
#pragma unroll
                for (int c = 0; c < 4; c++)
                    outr[r][c] += sa[r][c] + eci * ews[o0 + c];
            }
        }
        __syncthreads();
    }

    // ---- skip GEMM: sk = x @ Ws^T ----
    float sk[2][4];
#pragma unroll
    for (int r = 0; r < 2; r++)
#pragma unroll
        for (int c = 0; c < 4; c++) sk[r][c] = 0.f;

    for (int l = t; l < 64 * 32; l += THREADS) {
        int kk = l & 31, o = l >> 5;
        wt0[kk * WTPAD + o] = Ws[o * CDIM + kk];
    }
    __syncthreads();

    for (int kb = 0; kb < 8; kb++) {
        const int k0 = kb * 32;
        float* cur = (kb & 1) ? wt1 : wt0;
        float* nxt = (kb & 1) ? wt0 : wt1;
        if (kb < 7) {
            const int kn = k0 + 32;
            for (int l = t; l < 64 * 32; l += THREADS) {
                int kk = l & 31, o = l >> 5;
                nxt[kk * WTPAD + o] = Ws[o * CDIM + kn + kk];
            }
        }
#pragma unroll
        for (int kk = 0; kk < 32; kk += 4) {
            float4 a4[2];
#pragma unroll
            for (int r = 0; r < 2; r++)
                a4[r] = *(const float4*)&xs[(i02 + r) * XPAD + k0 + kk];
#pragma unroll
            for (int u = 0; u < 4; u++) {
                const float* brow = &cur[(kk + u) * WTPAD + o0];
                float2 bl = *(const float2*)(brow);
                float2 bh = *(const float2*)(brow + 2);
#pragma unroll
                for (int r = 0; r < 2; r++) {
                    float av = ((const float*)&a4[r])[u];
                    sk[r][0] += av * bl.x;
                    sk[r][1] += av * bl.y;
                    sk[r][2] += av * bh.x;
                    sk[r][3] += av * bh.y;
                }
            }
        }
        __syncthreads();
    }

    // ---- epilogue ----
    {
        float4* og = (float4*)(out + (size_t)b * (NN * OO));
#pragma unroll
        for (int r = 0; r < 2; r++) {
            float4 res;
            float v0 = outr[r][0] * 0.125f + sk[r][0] + bs[o0 + 0];
            float v1 = outr[r][1] * 0.125f + sk[r][1] + bs[o0 + 1];
            float v2 = outr[r][2] * 0.125f + sk[r][2] + bs[o0 + 2];
            float v3 = outr[r][3] * 0.125f + sk[r][3] + bs[o0 + 3];
            res.x = (v0 > 0.1f) ? 1.f / (1.f + __expf(-v0)) : 0.f;
            res.y = (v1 > 0.1f) ? 1.f / (1.f + __expf(-v1)) : 0.f;
            res.z = (v2 > 0.1f) ? 1.f / (1.f + __expf(-v2)) : 0.f;
            res.w = (v3 > 0.1f) ? 1.f / (1.f + __expf(-v3)) : 0.f;
            og[(i02 + r) * 16 + tx8] = res;
        }
    }
}

// ============================================================================
// launch
// ============================================================================
extern "C" void kernel_launch(void* const* d_in, const int* in_sizes, int n_in,
                              void* d_out, int out_size)
{
    const float* ctx = (const float*)d_in[0];
    const float* adj = (const float*)d_in[1];
    const float* Wq  = (const float*)d_in[2];
    const float* bq  = (const float*)d_in[3];
    const float* Wk  = (const float*)d_in[4];
    const float* bk  = (const float*)d_in[5];
    const float* Wv  = (const float*)d_in[6];
    const float* bv  = (const float*)d_in[7];
    const float* We  = (const float*)d_in[8];
    const float* Ws  = (const float*)d_in[9];
    const float* bs  = (const float*)d_in[10];
    float* out = (float*)d_out;

    // K1: 3xTF32 tensor-core QKV projection
    cudaFuncSetAttribute(qkv_gemm_kernel,
                         cudaFuncAttributeMaxDynamicSharedMemorySize, K1_SMEM_BYTES);
    qkv_gemm_kernel<<<dim3(512, 12), K1_THREADS, K1_SMEM_BYTES>>>(ctx, Wq, Wk, Wv);

    // K2: attention + skip + epilogue
    const int smem_bytes = SMEM_FLOATS * sizeof(float);
    cudaFuncSetAttribute(attn_kernel,
                         cudaFuncAttributeMaxDynamicSharedMemorySize, smem_bytes);
    attn_kernel<<<BB, THREADS, smem_bytes>>>(ctx, adj, bq, bk, bv, We, Ws, bs, out);
}

// round 16
// speedup vs baseline: 1.4446x; 1.1890x over previous
#include <cuda_runtime.h>
#include <cstdint>

// ============================================================================
// Problem constants
// ============================================================================
#define BB    1024
#define NN    64
#define CDIM  256
#define HH    8
#define OO    64

// ============================================================================
// Scratch (device global -- allocation-free per harness rules)
// ============================================================================
#define NXROWS (BB * NN)           // 65536
__device__ float g_qkv[(size_t)NXROWS * 1536];   // [65536][1536] fp32

// ============================================================================
// tf32 helpers (base-target PTX, sm_80+; no 'a' features)
// ============================================================================
__device__ __forceinline__ uint32_t f2tf32(float v) {
    uint32_t r;
    asm("cvt.rna.tf32.f32 %0, %1;" : "=r"(r) : "f"(v));
    return r;
}

__device__ __forceinline__ void mma_tf32(float c[4], const uint32_t a[4],
                                         uint32_t b0, uint32_t b1) {
    asm volatile(
        "mma.sync.aligned.m16n8k8.row.col.f32.tf32.tf32.f32 "
        "{%0,%1,%2,%3}, {%4,%5,%6,%7}, {%8,%9}, {%0,%1,%2,%3};"
        : "+f"(c[0]), "+f"(c[1]), "+f"(c[2]), "+f"(c[3])
        : "r"(a[0]), "r"(a[1]), "r"(a[2]), "r"(a[3]), "r"(b0), "r"(b1));
}

// ============================================================================
// K1: QKV projection GEMM, 3xTF32 via mma.sync
//   D[65536,1536] = X[65536,256] @ W^T  (Wq rows 0-511, Wk, Wv)
//   CTA tile M=128, N=128; K chunks of 64, register-staged pipeline.
//   512 threads: warp grid 4x4, warp tile 32x32.
// ============================================================================
#define K1_THREADS 512
#define APAD 68                       // u32 row stride (4 mod 32 banks)
// smem (u32): Ah[128*68] Ar Bh Br  => 4*8704 = 34816 u32 = 139264 B
#define K1_AH 0
#define K1_AR 8704
#define K1_BH 17408
#define K1_BR 26112
#define K1_SMEM_BYTES (34816 * 4)

__global__ __launch_bounds__(K1_THREADS, 1)
void qkv_gemm_kernel(const float* __restrict__ ctx,
                     const float* __restrict__ Wq,
                     const float* __restrict__ Wk,
                     const float* __restrict__ Wv)
{
    extern __shared__ uint32_t smu[];
    uint32_t* Ah = smu + K1_AH;
    uint32_t* Ar = smu + K1_AR;
    uint32_t* Bh = smu + K1_BH;
    uint32_t* Br = smu + K1_BR;

    const int t    = threadIdx.x;
    const int lane = t & 31;
    const int wid  = t >> 5;
    const int m0   = blockIdx.x * 128;
    const int by   = blockIdx.y;
    const int n0g  = by * 128;

    const float* Wsrc;
    int nrow0;
    if (by < 4)      { Wsrc = Wq; nrow0 = n0g; }
    else if (by < 8) { Wsrc = Wk; nrow0 = n0g - 512; }
    else             { Wsrc = Wv; nrow0 = n0g - 1024; }

    // warp grid 4x4: warp tile 32x32
    const int m_off = (wid >> 2) * 32;
    const int n_off = (wid & 3) * 32;
    const int gq = lane >> 2;   // groupID
    const int tg = lane & 3;    // thread-in-group

    float acc[2][4][4];
#pragma unroll
    for (int m = 0; m < 2; m++)
#pragma unroll
        for (int n = 0; n < 4; n++)
#pragma unroll
            for (int u = 0; u < 4; u++) acc[m][n][u] = 0.f;

    // register staging: 4 float4 for A + 4 for B per chunk
    float4 avr[4], bvr[4];

    // ---- load chunk 0 ----
#pragma unroll
    for (int j = 0; j < 4; j++) {
        int l = t + j * K1_THREADS;
        int row = l >> 4, c4 = (l & 15) * 4;
        avr[j] = *(const float4*)(ctx + (size_t)(m0 + row) * CDIM + c4);
        bvr[j] = *(const float4*)(Wsrc + (size_t)(nrow0 + row) * CDIM + c4);
    }
    // ---- STS chunk 0 (convert fp32 -> tf32 hi/lo) ----
#pragma unroll
    for (int j = 0; j < 4; j++) {
        int l = t + j * K1_THREADS;
        int row = l >> 4, c4 = (l & 15) * 4;
#pragma unroll
        for (int u = 0; u < 4; u++) {
            float va = ((const float*)&avr[j])[u];
            uint32_t ha = f2tf32(va);
            Ah[row * APAD + c4 + u] = ha;
            Ar[row * APAD + c4 + u] = f2tf32(va - __uint_as_float(ha));
            float vb = ((const float*)&bvr[j])[u];
            uint32_t hb = f2tf32(vb);
            Bh[row * APAD + c4 + u] = hb;
            Br[row * APAD + c4 + u] = f2tf32(vb - __uint_as_float(hb));
        }
    }
    __syncthreads();

    for (int kc = 0; kc < 4; ++kc) {
        // ---- issue LDG for next chunk (overlaps with MMA phase) ----
        if (kc < 3) {
            const int kn = (kc + 1) * 64;
#pragma unroll
            for (int j = 0; j < 4; j++) {
                int l = t + j * K1_THREADS;
                int row = l >> 4, c4 = (l & 15) * 4;
                avr[j] = *(const float4*)(ctx + (size_t)(m0 + row) * CDIM + kn + c4);
                bvr[j] = *(const float4*)(Wsrc + (size_t)(nrow0 + row) * CDIM + kn + c4);
            }
        }

        // ---- MMA phase: 8 k-steps of 8 over this chunk ----
#pragma unroll 1
        for (int k8 = 0; k8 < 8; ++k8) {
            const int kb = k8 * 8;
            uint32_t ah[2][4], ar[2][4];
#pragma unroll
            for (int m = 0; m < 2; m++) {
                int r0 = (m_off + m * 16 + gq) * APAD;
                int c0 = kb + tg;
                ah[m][0] = Ah[r0 + c0];
                ah[m][1] = Ah[r0 + 8 * APAD + c0];
                ah[m][2] = Ah[r0 + c0 + 4];
                ah[m][3] = Ah[r0 + 8 * APAD + c0 + 4];
                ar[m][0] = Ar[r0 + c0];
                ar[m][1] = Ar[r0 + 8 * APAD + c0];
                ar[m][2] = Ar[r0 + c0 + 4];
                ar[m][3] = Ar[r0 + 8 * APAD + c0 + 4];
            }
#pragma unroll
            for (int n = 0; n < 4; n++) {
                int nr = (n_off + n * 8 + gq) * APAD;
                int bc = kb + tg;
                uint32_t bh0 = Bh[nr + bc], bh1 = Bh[nr + bc + 4];
                uint32_t br0 = Br[nr + bc], br1 = Br[nr + bc + 4];
#pragma unroll
                for (int m = 0; m < 2; m++) {
                    mma_tf32(acc[m][n], ah[m], bh0, bh1);   // hi*hi
                    mma_tf32(acc[m][n], ah[m], br0, br1);   // hi*lo
                    mma_tf32(acc[m][n], ar[m], bh0, bh1);   // lo*hi
                }
            }
        }
        __syncthreads();   // all warps done reading this chunk

        // ---- STS next chunk ----
        if (kc < 3) {
#pragma unroll
            for (int j = 0; j < 4; j++) {
                int l = t + j * K1_THREADS;
                int row = l >> 4, c4 = (l & 15) * 4;
#pragma unroll
                for (int u = 0; u < 4; u++) {
                    float va = ((const float*)&avr[j])[u];
                    uint32_t ha = f2tf32(va);
                    Ah[row * APAD + c4 + u] = ha;
                    Ar[row * APAD + c4 + u] = f2tf32(va - __uint_as_float(ha));
                    float vb = ((const float*)&bvr[j])[u];
                    uint32_t hb = f2tf32(vb);
                    Bh[row * APAD + c4 + u] = hb;
                    Br[row * APAD + c4 + u] = f2tf32(vb - __uint_as_float(hb));
                }
            }
            __syncthreads();
        }
    }

    // ---- writeback: accums -> smem (transpose) -> coalesced gmem ----
    float* Ds = (float*)smu;   // [128][132] floats = 67584 B
#pragma unroll
    for (int m = 0; m < 2; m++) {
        int r0 = m_off + m * 16 + gq;
#pragma unroll
        for (int n = 0; n < 4; n++) {
            int cb = n_off + n * 8 + 2 * tg;
            Ds[r0 * 132 + cb]           = acc[m][n][0];
            Ds[r0 * 132 + cb + 1]       = acc[m][n][1];
            Ds[(r0 + 8) * 132 + cb]     = acc[m][n][2];
            Ds[(r0 + 8) * 132 + cb + 1] = acc[m][n][3];
        }
    }
    __syncthreads();
    for (int l = t; l < 16384; l += K1_THREADS) {
        int r = l >> 7, c = l & 127;
        g_qkv[(size_t)(m0 + r) * 1536 + n0g + c] = Ds[r * 132 + c];
    }
}

// ============================================================================
// K2: attention + skip + epilogue; per-head q/k/v double-buffered via regs
// ============================================================================
#define THREADS 512
#define XPAD  260
#define QPAD  68
#define WTPAD 198

#define OFF_XS   0
#define OFF_WT0  (OFF_XS + 64*XPAD)
#define OFF_WT1  (OFF_WT0 + 32*WTPAD)
#define OFF_QS   (OFF_WT1 + 32*WTPAD)
#define OFF_KS   (OFF_QS + 64*QPAD)
#define OFF_VS   (OFF_KS + 64*QPAD)
#define OFF_SS   (OFF_VS + 64*QPAD)
#define OFF_AD   (OFF_SS + 64*QPAD)
#define OFF_EC   (OFF_AD + 64*QPAD)
#define OFF_QE   (OFF_EC + 64)
#define OFF_EW   (OFF_QE + 64)
#define SMEM_FLOATS (OFF_EW + 64)

__global__ __launch_bounds__(THREADS, 1)
void attn_kernel(const float* __restrict__ ctx, const float* __restrict__ adj,
                 const float* __restrict__ bq, const float* __restrict__ bk,
                 const float* __restrict__ bv, const float* __restrict__ We,
                 const float* __restrict__ Ws, const float* __restrict__ bs,
                 float* __restrict__ out)
{
    extern __shared__ float sm[];
    float* xs   = sm + OFF_XS;
    float* wt0  = sm + OFF_WT0;
    float* wt1  = sm + OFF_WT1;
    float* qs   = sm + OFF_QS;
    float* ks   = sm + OFF_KS;
    float* vs   = sm + OFF_VS;
    float* ss   = sm + OFF_SS;
    float* ad   = sm + OFF_AD;
    float* ec   = sm + OFF_EC;
    float* qe   = sm + OFF_QE;
    float* ews  = sm + OFF_EW;

    const int b = blockIdx.x;
    const int t = threadIdx.x;

    const int tx8 = t & 15;
    const int ty8 = t >> 4;
    const int i02 = ty8 * 2;
    const int o0  = tx8 * 4;

    const int rw  = t >> 3;
    const int oct = t & 7;

    // per-head prefetch mapping: l = t + j*512, j=0..1; row i = l>>4, col o4
    const int pf_i  = t >> 4;          // j=0 row
    const int pf_o  = (t & 15) * 4;

    // ---- load x_b (for skip GEMM) ----
    {
        const float4* xg = (const float4*)(ctx + (size_t)b * (NN * CDIM));
        for (int l = t; l < NN * CDIM / 4; l += THREADS) {
            int e = l * 4;
            int i = e >> 8;
            int k = e & 255;
            float4 v4 = xg[l];
            float* d = &xs[i * XPAD + k];
            d[0] = v4.x; d[1] = v4.y; d[2] = v4.z; d[3] = v4.w;
        }
    }
    // ---- load adjT ----
    {
        const float* ag = adj + (size_t)b * (NN * NN);
        for (int l = t; l < NN * NN; l += THREADS) {
            int j = l >> 6, i = l & 63;
            ad[i * QPAD + j] = ag[l];
        }
    }

    float outr[2][4];
#pragma unroll
    for (int r = 0; r < 2; r++)
#pragma unroll
        for (int c = 0; c < 4; c++) outr[r][c] = 0.f;

    const float* qkv_b = g_qkv + (size_t)(b * NN) * 1536;

    // ---- prefetch head 0 q/k/v into registers ----
    float4 pq[2], pk[2], pv[2];
#pragma unroll
    for (int j = 0; j < 2; j++) {
        const float* row = qkv_b + (size_t)(pf_i + j * 32) * 1536 + pf_o;
        pq[j] = *(const float4*)(row);
        pk[j] = *(const float4*)(row + 512);
        pv[j] = *(const float4*)(row + 1024);
    }

    for (int h = 0; h < HH; ++h) {
        const int hbase = h * 64;
        if (t < 64) ews[t] = We[hbase + t];

        // ---- stash prefetched q/k/v (+bias, float4) ----
        {
            float4 b4q = *(const float4*)(bq + hbase + pf_o);
            float4 b4k = *(const float4*)(bk + hbase + pf_o);
            float4 b4v = *(const float4*)(bv + hbase + pf_o);
#pragma unroll
            for (int j = 0; j < 2; j++) {
                int i = pf_i + j * 32;
                float4 q4 = pq[j], k4 = pk[j], v4 = pv[j];
                q4.x += b4q.x; q4.y += b4q.y; q4.z += b4q.z; q4.w += b4q.w;
                k4.x += b4k.x; k4.y += b4k.y; k4.z += b4k.z; k4.w += b4k.w;
                v4.x += b4v.x; v4.y += b4v.y; v4.z += b4v.z; v4.w += b4v.w;
                *(float4*)&qs[i * QPAD + pf_o] = q4;
                *(float4*)&ks[i * QPAD + pf_o] = k4;
                *(float4*)&vs[i * QPAD + pf_o] = v4;
            }
        }
        __syncthreads();

        // ---- prefetch head h+1 (LDG overlaps this head's compute) ----
        if (h < HH - 1) {
            const int hn = hbase + 64;
#pragma unroll
            for (int j = 0; j < 2; j++) {
                const float* row = qkv_b + (size_t)(pf_i + j * 32) * 1536 + hn + pf_o;
                pq[j] = *(const float4*)(row);
                pk[j] = *(const float4*)(row + 512);
                pv[j] = *(const float4*)(row + 1024);
            }
        }

        // ---- qe[i] = q_i . ew ----
        {
            const float* qrow = &qs[rw * QPAD + oct * 8];
            const float* erow = &ews[oct * 8];
            float p = 0.f;
#pragma unroll
            for (int u = 0; u < 8; u++) p += qrow[u] * erow[u];
            p += __shfl_xor_sync(0xffffffffu, p, 1);
            p += __shfl_xor_sync(0xffffffffu, p, 2);
            p += __shfl_xor_sync(0xffffffffu, p, 4);
            if (oct == 0) qe[rw] = p;
        }
        __syncthreads();

        // ---- scores S = (q k^T + adjT*qe)/8 ----
        {
            float sa[2][4];
#pragma unroll
            for (int r = 0; r < 2; r++)
#pragma unroll
                for (int c = 0; c < 4; c++) sa[r][c] = 0.f;
#pragma unroll
            for (int o = 0; o < 64; o += 4) {
                float4 aq[2], bk4[4];
#pragma unroll
                for (int r = 0; r < 2; r++) aq[r]  = *(const float4*)&qs[(i02 + r) * QPAD + o];
#pragma unroll
                for (int c = 0; c < 4; c++) bk4[c] = *(const float4*)&ks[(o0 + c) * QPAD + o];
#pragma unroll
                for (int r = 0; r < 2; r++)
#pragma unroll
                    for (int c = 0; c < 4; c++)
                        sa[r][c] += aq[r].x * bk4[c].x + aq[r].y * bk4[c].y
                                  + aq[r].z * bk4[c].z + aq[r].w * bk4[c].w;
            }
#pragma unroll
            for (int r = 0; r < 2; r++) {
                float qei = qe[i02 + r];
#pragma unroll
                for (int c = 0; c < 4; c++)
                    ss[(i02 + r) * QPAD + o0 + c] =
                        0.125f * (sa[r][c] + ad[(i02 + r) * QPAD + o0 + c] * qei);
            }
        }
        __syncthreads();

        // ---- softmax + ecoef ----
        {
            float* row = &ss[rw * QPAD + oct * 8];
            const float* arow = &ad[rw * QPAD + oct * 8];
            float m = -1e30f;
#pragma unroll
            for (int u = 0; u < 8; u++) m = fmaxf(m, row[u]);
            m = fmaxf(m, __shfl_xor_sync(0xffffffffu, m, 1));
            m = fmaxf(m, __shfl_xor_sync(0xffffffffu, m, 2));
            m = fmaxf(m, __shfl_xor_sync(0xffffffffu, m, 4));
            float e[8];
            float s = 0.f;
#pragma unroll
            for (int u = 0; u < 8; u++) { e[u] = __expf(row[u] - m); s += e[u]; }
            s += __shfl_xor_sync(0xffffffffu, s, 1);
            s += __shfl_xor_sync(0xffffffffu, s, 2);
            s += __shfl_xor_sync(0xffffffffu, s, 4);
            float rinv = 1.f / s;
            float pc = 0.f;
#pragma unroll
            for (int u = 0; u < 8; u++) {
                float al = e[u] * rinv;
                row[u] = al;
                pc += al * arow[u];
            }
            pc += __shfl_xor_sync(0xffffffffu, pc, 1);
            pc += __shfl_xor_sync(0xffffffffu, pc, 2);
            pc += __shfl_xor_sync(0xffffffffu, pc, 4);
            if (oct == 0) ec[rw] = pc;
        }
        __syncthreads();

        // ---- out += alpha @ v + ec_i * ew_o ----
        {
            float sa[2][4];
#pragma unroll
            for (int r = 0; r < 2; r++)
#pragma unroll
                for (int c = 0; c < 4; c++) sa[r][c] = 0.f;
#pragma unroll 8
            for (int j = 0; j < 64; j++) {
                float4 bv4 = *(const float4*)&vs[j * QPAD + o0];
#pragma unroll
                for (int r = 0; r < 2; r++) {
                    float al = ss[(i02 + r) * QPAD + j];
                    sa[r][0] += al * bv4.x;
                    sa[r][1] += al * bv4.y;
                    sa[r][2] += al * bv4.z;
                    sa[r][3] += al * bv4.w;
                }
            }
#pragma unroll
            for (int r = 0; r < 2; r++) {
                float eci = ec[i02 + r];
#pragma unroll
                for (int c = 0; c < 4; c++)
                    outr[r][c] += sa[r][c] + eci * ews[o0 + c];
            }
        }
        __syncthreads();
    }

    // ---- skip GEMM: sk = x @ Ws^T ----
    float sk[2][4];
#pragma unroll
    for (int r = 0; r < 2; r++)
#pragma unroll
        for (int c = 0; c < 4; c++) sk[r][c] = 0.f;

    for (int l = t; l < 64 * 32; l += THREADS) {
        int kk = l & 31, o = l >> 5;
        wt0[kk * WTPAD + o] = Ws[o * CDIM + kk];
    }
    __syncthreads();

    for (int kb = 0; kb < 8; kb++) {
        const int k0 = kb * 32;
        float* cur = (kb & 1) ? wt1 : wt0;
        float* nxt = (kb & 1) ? wt0 : wt1;
        if (kb < 7) {
            const int kn = k0 + 32;
            for (int l = t; l < 64 * 32; l += THREADS) {
                int kk = l & 31, o = l >> 5;
                nxt[kk * WTPAD + o] = Ws[o * CDIM + kn + kk];
            }
        }
#pragma unroll
        for (int kk = 0; kk < 32; kk += 4) {
            float4 a4[2];
#pragma unroll
            for (int r = 0; r < 2; r++)
                a4[r] = *(const float4*)&xs[(i02 + r) * XPAD + k0 + kk];
#pragma unroll
            for (int u = 0; u < 4; u++) {
                const float* brow = &cur[(kk + u) * WTPAD + o0];
                float2 bl = *(const float2*)(brow);
                float2 bh = *(const float2*)(brow + 2);
#pragma unroll
                for (int r = 0; r < 2; r++) {
                    float av = ((const float*)&a4[r])[u];
                    sk[r][0] += av * bl.x;
                    sk[r][1] += av * bl.y;
                    sk[r][2] += av * bh.x;
                    sk[r][3] += av * bh.y;
                }
            }
        }
        __syncthreads();
    }

    // ---- epilogue ----
    {
        float4* og = (float4*)(out + (size_t)b * (NN * OO));
#pragma unroll
        for (int r = 0; r < 2; r++) {
            float4 res;
            float v0 = outr[r][0] * 0.125f + sk[r][0] + bs[o0 + 0];
            float v1 = outr[r][1] * 0.125f + sk[r][1] + bs[o0 + 1];
            float v2 = outr[r][2] * 0.125f + sk[r][2] + bs[o0 + 2];
            float v3 = outr[r][3] * 0.125f + sk[r][3] + bs[o0 + 3];
            res.x = (v0 > 0.1f) ? 1.f / (1.f + __expf(-v0)) : 0.f;
            res.y = (v1 > 0.1f) ? 1.f / (1.f + __expf(-v1)) : 0.f;
            res.z = (v2 > 0.1f) ? 1.f / (1.f + __expf(-v2)) : 0.f;
            res.w = (v3 > 0.1f) ? 1.f / (1.f + __expf(-v3)) : 0.f;
            og[(i02 + r) * 16 + tx8] = res;
        }
    }
}

// ============================================================================
// launch
// ============================================================================
extern "C" void kernel_launch(void* const* d_in, const int* in_sizes, int n_in,
                              void* d_out, int out_size)
{
    const float* ctx = (const float*)d_in[0];
    const float* adj = (const float*)d_in[1];
    const float* Wq  = (const float*)d_in[2];
    const float* bq  = (const float*)d_in[3];
    const float* Wk  = (const float*)d_in[4];
    const float* bk  = (const float*)d_in[5];
    const float* Wv  = (const float*)d_in[6];
    const float* bv  = (const float*)d_in[7];
    const float* We  = (const float*)d_in[8];
    const float* Ws  = (const float*)d_in[9];
    const float* bs  = (const float*)d_in[10];
    float* out = (float*)d_out;

    // K1: 3xTF32 tensor-core QKV projection (pipelined)
    cudaFuncSetAttribute(qkv_gemm_kernel,
                         cudaFuncAttributeMaxDynamicSharedMemorySize, K1_SMEM_BYTES);
    qkv_gemm_kernel<<<dim3(512, 12), K1_THREADS, K1_SMEM_BYTES>>>(ctx, Wq, Wk, Wv);

    // K2: attention + skip + epilogue (head-loop double-buffered)
    const int smem_bytes = SMEM_FLOATS * sizeof(float);
    cudaFuncSetAttribute(attn_kernel,
                         cudaFuncAttributeMaxDynamicSharedMemorySize, smem_bytes);
    attn_kernel<<<BB, THREADS, smem_bytes>>>(ctx, adj, bq, bk, bv, We, Ws, bs, out);
}